// round 10
// baseline (speedup 1.0000x reference)
#include <cuda_runtime.h>
#include <cuda_fp16.h>
#include <stdint.h>

// GraphMatcher power iteration, GB300/sm_100a.
// K stored once as u8 = round(255*K^2) (squared domain doubles precision at the
// large-K winners; sqrt per message restores). One CTA per graph, 768 threads
// (24 warps, 80-reg cap): dst-sorted edge slots keep the dst node's packed x^2
// block in registers across runs, PLUS depth-1 register prefetch of the next
// edge's K row (the 64-reg cap at 1024 thr forced choosing one; 768 thr fits
// both). 3 barriers/iter: all warps redundantly reduce the 24 norm partials.

#define BSZ      128
#define NV       32
#define EPG      256
#define EDGES_G  (EPG + NV)          // 288
#define E_RAND   (BSZ * EPG)         // 32768
#define E_TOT    (E_RAND + BSZ * NV) // 36864
#define NN       (NV * NV)           // 1024
#define ITERS    20
#define THREADS  768
#define WARPS    24
#define EPW      (EDGES_G / WARPS)   // 12 edges per warp

// 37.75 MB u8 scratch for quantized K^2
__device__ uint8_t g_K8[(size_t)E_TOT * NN];

// ---------------------------------------------------------------------------
// Quantize K (fp32 in [0,1)) -> u8 fixed point of K^2. 16 elements per thread.
// ---------------------------------------------------------------------------
__global__ void k_convert(const float* __restrict__ K) {
    size_t i = ((size_t)blockIdx.x * blockDim.x + threadIdx.x) * 16;
    if (i >= (size_t)E_TOT * NN) return;
    uint32_t w[4];
    #pragma unroll
    for (int q = 0; q < 4; q++) {
        const float4 a = *(const float4*)(K + i + q * 4);
        uint32_t b0 = __float2uint_rn(a.x * a.x * 255.f);
        uint32_t b1 = __float2uint_rn(a.y * a.y * 255.f);
        uint32_t b2 = __float2uint_rn(a.z * a.z * 255.f);
        uint32_t b3 = __float2uint_rn(a.w * a.w * 255.f);
        w[q] = b0 | (b1 << 8) | (b2 << 16) | (b3 << 24);
    }
    *(uint4*)(g_K8 + i) = make_uint4(w[0], w[1], w[2], w[3]);
}

// Global K row index for per-graph edge k (random edges then self loops).
__device__ __forceinline__ int krow(int g, int k) {
    return (k < EPG) ? (g * EPG + k) : (E_RAND + g * NV + (k - EPG));
}

// All-lanes total of the 24 per-warp partials in red[] (no extra barrier:
// 1 broadcast LDS + 5 butterfly shuffles, every warp does it redundantly).
__device__ __forceinline__ float reduce24(const float* __restrict__ red, int lane) {
    float w = (lane < WARPS) ? red[lane] : 0.f;
    #pragma unroll
    for (int o = 16; o > 0; o >>= 1) w += __shfl_xor_sync(0xFFFFFFFFu, w, o);
    return w;
}

// 4 u8 K-values vs one uint4 of packed x^2 data (X01,Y01,X23,Y23 as half2 bits).
// h = 1024+v exactly (bits 0x6400|v); hfma2(h, X, -1024*X) = v*X, one rounding.
__device__ __forceinline__ void quad_op(uint32_t kw, uint4 xv,
                                        __half2& ma, __half2& mb) {
    uint32_t h01u = __byte_perm(kw, 0x64646464u, 0x4140);
    uint32_t h23u = __byte_perm(kw, 0x64646464u, 0x4342);
    __half2 h01 = *reinterpret_cast<__half2*>(&h01u);
    __half2 h23 = *reinterpret_cast<__half2*>(&h23u);
    __half2 X01 = *reinterpret_cast<__half2*>(&xv.x);
    __half2 Y01 = *reinterpret_cast<__half2*>(&xv.y);
    __half2 X23 = *reinterpret_cast<__half2*>(&xv.z);
    __half2 Y23 = *reinterpret_cast<__half2*>(&xv.w);
    ma = __hmax2(ma, __hfma2(h01, X01, Y01));
    mb = __hmax2(mb, __hfma2(h23, X23, Y23));
}

// ---------------------------------------------------------------------------
// SMEM layout (bytes):
//   msgs   [0      ..  36864)  288*32 fp32
//   xq     [36864  ..  40960)  32 nodes * 8 quad-uint4 (packed x^2 half2)
//   outv   [40960  ..  45056)  1024 fp32 (unnormalized x)
//   slots  [45056  ..  46208)  288 u32: row(0..15) | k(16..24) | d(25..29) | flag(30)
//   esrc   [46208  ..  46784)  288 u16
//   edst   [46784  ..  47360)  288 u16
//   glist  [47360  ..  47936)  288 u16
//   dsort  [47936  ..  48512)  288 u16 (scratch for dst sort)
//   goff   [48512  ..  48644)  33 int
//   red    [48644  ..  48772)  32 fp32
// ---------------------------------------------------------------------------
#define SMEM_BYTES 48772

__global__ __launch_bounds__(THREADS, 1) void k_mpm(
    const void* __restrict__ ei_raw,
    const float* __restrict__ x_in,
    float* __restrict__ out)
{
    extern __shared__ char sm[];
    float*    msgs   = (float*)sm;
    uint4*    xq     = (uint4*)(sm + 36864);
    float*    outv   = (float*)(sm + 40960);
    uint32_t* slots  = (uint32_t*)(sm + 45056);
    uint16_t* esrc   = (uint16_t*)(sm + 46208);
    uint16_t* edst   = (uint16_t*)(sm + 46784);
    uint16_t* glist  = (uint16_t*)(sm + 47360);
    uint16_t* dsort  = (uint16_t*)(sm + 47936);
    int*      goff   = (int*)(sm + 48512);
    float*    red    = (float*)(sm + 48644);

    const int tid  = threadIdx.x;
    const int g    = blockIdx.x;
    const int wid  = tid >> 5, lane = tid & 31;

    // ---- int32/int64 detection (warp 0, broadcast through red[31]) ----
    if (tid < 32) {
        unsigned long long v = ((const unsigned long long*)ei_raw)[1 + (lane & 15)];
        unsigned bal = __ballot_sync(0xFFFFFFFFu, v < 4096ull);
        if (lane == 0) red[31] = (bal == 0xFFFFFFFFu) ? 1.0f : 0.0f;
    }
    __syncthreads();
    const int is64 = (red[31] != 0.0f);

    // ---- per-graph edge tables ----
    if (tid < EDGES_G) {
        int k = tid;
        int e = krow(g, k);
        long long s, d;
        if (is64) {
            const long long* p = (const long long*)ei_raw;
            s = p[e]; d = p[E_TOT + e];
        } else {
            const int* p = (const int*)ei_raw;
            s = p[e]; d = p[E_TOT + e];
        }
        esrc[k] = (uint16_t)(s - (long long)g * NV);
        edst[k] = (uint16_t)(d - (long long)g * NV);
    }
    __syncthreads();

    // ---- build (a) per-src gather lists, (b) dst-sorted slot words ----
    if (tid == 0) {
        // (a) segment lists by src
        int cnt[NV];
        #pragma unroll
        for (int s = 0; s < NV; s++) cnt[s] = 0;
        for (int k = 0; k < EDGES_G; k++) cnt[esrc[k]]++;
        int off = 0;
        for (int s = 0; s < NV; s++) { goff[s] = off; off += cnt[s]; cnt[s] = goff[s]; }
        goff[NV] = off;
        for (int k = 0; k < EDGES_G; k++) { int s = esrc[k]; glist[cnt[s]++] = (uint16_t)k; }
    } else if (tid == 32) {
        // (b) counting sort of edges by dst (separate warp, runs concurrently)
        int dc[NV];
        #pragma unroll
        for (int d = 0; d < NV; d++) dc[d] = 0;
        for (int k = 0; k < EDGES_G; k++) dc[edst[k]]++;
        int off = 0;
        #pragma unroll
        for (int d = 0; d < NV; d++) { int c = dc[d]; dc[d] = off; off += c; }
        for (int k = 0; k < EDGES_G; k++) { int d = edst[k]; dsort[dc[d]++] = (uint16_t)k; }
        int dprev = -1;
        for (int idx = 0; idx < EDGES_G; idx++) {
            int k = dsort[idx];
            int d = edst[k];
            uint32_t flag = ((idx % EPW) == 0 || d != dprev) ? 1u : 0u;
            slots[idx] = (uint32_t)krow(g, k) | ((uint32_t)k << 16)
                       | ((uint32_t)d << 25) | (flag << 30);
            dprev = d;
        }
    }

    // ---- x0: load raw x, per-warp norm partial -> red[wid] ----
    {
        float part = 0.f;
        for (int t = tid; t < NN; t += THREADS) {
            float v = x_in[(size_t)g * NN + t];
            outv[t] = v;
            part += v * v;
        }
        #pragma unroll
        for (int o = 16; o > 0; o >>= 1) part += __shfl_down_sync(0xFFFFFFFFu, part, o);
        if (lane == 0) red[wid] = part;
    }

    const __half2 NEG1024 = __float2half2_rn(-1024.f);
    const int sbase = wid * EPW;

    for (int it = 0; it < ITERS; it++) {
        __syncthreads();                       // A: partials + outv (+tables) visible
        float inv = rsqrtf(reduce24(red, lane));

        // ---- pack x^2 as half2 quads: xq[node*8+q] = (X01,Y01,X23,Y23) ----
        if (tid < NV * 8) {
            int node = tid >> 3, q = tid & 7, j0 = q * 4;
            const float* xr = outv + node * NV + j0;
            float v0 = xr[0] * inv, v1 = xr[1] * inv, v2 = xr[2] * inv, v3 = xr[3] * inv;
            __half2 Xa = __floats2half2_rn(v0 * v0, v1 * v1);
            __half2 Xb = __floats2half2_rn(v2 * v2, v3 * v3);
            __half2 Ya = __hmul2(Xa, NEG1024);   // exact (power of two)
            __half2 Yb = __hmul2(Xb, NEG1024);
            uint4 w;
            w.x = *reinterpret_cast<uint32_t*>(&Xa);
            w.y = *reinterpret_cast<uint32_t*>(&Ya);
            w.z = *reinterpret_cast<uint32_t*>(&Xb);
            w.w = *reinterpret_cast<uint32_t*>(&Yb);
            xq[tid] = w;
        }
        __syncthreads();                       // B: xq visible

        // ---- phase 1: dst-sorted edges; xd reloaded on dst change; K prefetch ----
        // msg[e][i] = sqrt(max_j x2[dst][j] * K2[e][i][j])   (scale-free)
        {
            uint4 xd0, xd1, xd2, xd3, xd4, xd5, xd6, xd7;
            uint32_t sl = slots[sbase];
            uint4 q0, q1;
            {
                const uint4* p = (const uint4*)(g_K8 + (size_t)(sl & 0xFFFFu) * NN) + lane * 2;
                q0 = p[0]; q1 = p[1];
            }
            #pragma unroll
            for (int s = 0; s < EPW; s++) {
                // depth-1 prefetch: issue next edge's K before consuming current
                uint32_t sln;
                uint4 n0, n1;
                if (s + 1 < EPW) {
                    sln = slots[sbase + s + 1];
                    const uint4* pn = (const uint4*)(g_K8 + (size_t)(sln & 0xFFFFu) * NN) + lane * 2;
                    n0 = pn[0]; n1 = pn[1];
                }
                if (sl & (1u << 30)) {            // warp-uniform dst change
                    const uint4* xp = xq + ((sl >> 25) & 31u) * 8;
                    xd0 = xp[0]; xd1 = xp[1]; xd2 = xp[2]; xd3 = xp[3];
                    xd4 = xp[4]; xd5 = xp[5]; xd6 = xp[6]; xd7 = xp[7];
                }
                __half2 ma = __float2half2_rn(0.f), mb = ma;
                quad_op(q0.x, xd0, ma, mb);
                quad_op(q0.y, xd1, ma, mb);
                quad_op(q0.z, xd2, ma, mb);
                quad_op(q0.w, xd3, ma, mb);
                quad_op(q1.x, xd4, ma, mb);
                quad_op(q1.y, xd5, ma, mb);
                quad_op(q1.z, xd6, ma, mb);
                quad_op(q1.w, xd7, ma, mb);
                __half2 m2 = __hmax2(ma, mb);
                float m2f = __half2float(__hmax(__low2half(m2), __high2half(m2)));
                float msg;
                asm("sqrt.approx.f32 %0, %1;" : "=f"(msg) : "f"(m2f));
                msgs[((sl >> 16) & 0x1FFu) * NV + lane] = msg;
                if (s + 1 < EPW) { sl = sln; q0 = n0; q1 = n1; }
            }
        }
        __syncthreads();                       // C: msgs visible

        // ---- phase 2: segment-sum over src (two strided passes) + norm partial ----
        float part;
        {
            int s = tid >> 5, i = tid & 31;    // s warp-uniform -> broadcast list loads
            float a = 0.f;
            int b = goff[s], e2 = goff[s + 1];
            for (int q = b; q < e2; q++)
                a += msgs[(int)glist[q] * NV + i];
            outv[tid] = a;
            part = a * a;
        }
        if (tid < NN - THREADS) {              // remaining 256 elements (s = 24..31)
            int t = tid + THREADS;
            int s = t >> 5, i = t & 31;
            float a = 0.f;
            int b = goff[s], e2 = goff[s + 1];
            for (int q = b; q < e2; q++)
                a += msgs[(int)glist[q] * NV + i];
            outv[t] = a;
            part += a * a;
        }
        #pragma unroll
        for (int o = 16; o > 0; o >>= 1) part += __shfl_down_sync(0xFFFFFFFFu, part, o);
        if (lane == 0) red[wid] = part;
        // outv stays unnormalized; total published at next iteration's sync A
    }

    // ---- output: out[g, i, s] = x[g*32+s, i]  (transpose last two dims) ----
    __syncthreads();
    {
        float inv = rsqrtf(reduce24(red, lane));
        for (int t = tid; t < NN; t += THREADS) {
            int i = t >> 5, s = t & 31;
            out[(size_t)g * NN + t] = outv[s * NV + i] * inv;
        }
    }
}

// ---------------------------------------------------------------------------
extern "C" void kernel_launch(void* const* d_in, const int* in_sizes, int n_in,
                              void* d_out, int out_size) {
    const float* K  = (const float*)d_in[0];
    const void*  ei = d_in[1];
    const float* x  = (const float*)d_in[2];
    float* out = (float*)d_out;

    (void)in_sizes; (void)n_in; (void)out_size;

    cudaFuncSetAttribute(k_mpm, cudaFuncAttributeMaxDynamicSharedMemorySize, SMEM_BYTES);

    // 36864*1024 elems / 16 per thread / 256 per block = 9216 blocks (exact)
    k_convert<<<9216, 256>>>(K);

    k_mpm<<<BSZ, THREADS, SMEM_BYTES>>>(ei, x, out);
}

// round 11
// speedup vs baseline: 1.0587x; 1.0587x over previous
#include <cuda_runtime.h>
#include <cuda_fp16.h>
#include <stdint.h>

// GraphMatcher power iteration, GB300/sm_100a.
// K stored once as u8 = round(255*K^2) (squared domain; sqrt per message).
// One CTA per graph, 768 threads. Per warp: 12 dst-sorted edges, first 6 with
// K staged in SMEM (conflict-free half-split layout), last 6 streamed via LDG
// with depth-1 prefetch -- streamed working set 144 KB fits the L1 carveout,
// so K never touches L2 after warmup. dst-sorted slots keep the dst node's
// packed x^2 block in registers across equal-dst runs.

#define BSZ      128
#define NV       32
#define EPG      256
#define EDGES_G  (EPG + NV)          // 288
#define E_RAND   (BSZ * EPG)         // 32768
#define E_TOT    (E_RAND + BSZ * NV) // 36864
#define NN       (NV * NV)           // 1024
#define ITERS    20
#define THREADS  768
#define WARPS    24
#define EPW      (EDGES_G / WARPS)   // 12 edges per warp
#define SPW      6                   // staged edges per warp
#define NSTAGE_T (WARPS * SPW)       // 144 staged edges per CTA

// 37.75 MB u8 scratch for quantized K^2
__device__ uint8_t g_K8[(size_t)E_TOT * NN];

// ---------------------------------------------------------------------------
// Quantize K (fp32 in [0,1)) -> u8 fixed point of K^2. 16 elements per thread.
// ---------------------------------------------------------------------------
__global__ void k_convert(const float* __restrict__ K) {
    size_t i = ((size_t)blockIdx.x * blockDim.x + threadIdx.x) * 16;
    if (i >= (size_t)E_TOT * NN) return;
    uint32_t w[4];
    #pragma unroll
    for (int q = 0; q < 4; q++) {
        const float4 a = *(const float4*)(K + i + q * 4);
        uint32_t b0 = __float2uint_rn(a.x * a.x * 255.f);
        uint32_t b1 = __float2uint_rn(a.y * a.y * 255.f);
        uint32_t b2 = __float2uint_rn(a.z * a.z * 255.f);
        uint32_t b3 = __float2uint_rn(a.w * a.w * 255.f);
        w[q] = b0 | (b1 << 8) | (b2 << 16) | (b3 << 24);
    }
    *(uint4*)(g_K8 + i) = make_uint4(w[0], w[1], w[2], w[3]);
}

// Global K row index for per-graph edge k (random edges then self loops).
__device__ __forceinline__ int krow(int g, int k) {
    return (k < EPG) ? (g * EPG + k) : (E_RAND + g * NV + (k - EPG));
}

// All-lanes total of the 24 per-warp partials in red[] (no extra barrier).
__device__ __forceinline__ float reduce24(const float* __restrict__ red, int lane) {
    float w = (lane < WARPS) ? red[lane] : 0.f;
    #pragma unroll
    for (int o = 16; o > 0; o >>= 1) w += __shfl_xor_sync(0xFFFFFFFFu, w, o);
    return w;
}

// 4 u8 K-values vs one uint4 of packed x^2 data (X01,Y01,X23,Y23 as half2 bits).
// h = 1024+v exactly (bits 0x6400|v); hfma2(h, X, -1024*X) = v*X, one rounding.
__device__ __forceinline__ void quad_op(uint32_t kw, uint4 xv,
                                        __half2& ma, __half2& mb) {
    uint32_t h01u = __byte_perm(kw, 0x64646464u, 0x4140);
    uint32_t h23u = __byte_perm(kw, 0x64646464u, 0x4342);
    __half2 h01 = *reinterpret_cast<__half2*>(&h01u);
    __half2 h23 = *reinterpret_cast<__half2*>(&h23u);
    __half2 X01 = *reinterpret_cast<__half2*>(&xv.x);
    __half2 Y01 = *reinterpret_cast<__half2*>(&xv.y);
    __half2 X23 = *reinterpret_cast<__half2*>(&xv.z);
    __half2 Y23 = *reinterpret_cast<__half2*>(&xv.w);
    ma = __hmax2(ma, __hfma2(h01, X01, Y01));
    mb = __hmax2(mb, __hfma2(h23, X23, Y23));
}

// ---------------------------------------------------------------------------
// SMEM layout (bytes):
//   smK    [0      .. 147456)  staged K, half-split: [slot][h(0/1)*512 + lane*16]
//   msgs   [147456 .. 184320)  288*32 fp32
//   xq     [184320 .. 188416)  32 nodes * 8 quad-uint4 (packed x^2 half2)
//   outv   [188416 .. 192512)  1024 fp32 (unnormalized x)
//   slots  [192512 .. 193664)  288 u32: row(0..15) | k(16..24) | d(25..29) | flag(30)
//   esrc   [193664 .. 194240)  288 u16
//   edst   [194240 .. 194816)  288 u16
//   glist  [194816 .. 195392)  288 u16
//   dsort  [195392 .. 195968)  288 u16 (scratch)
//   goff   [195968 .. 196100)  33 int
//   red    [196100 .. 196228)  32 fp32
// ---------------------------------------------------------------------------
#define SMEM_BYTES 196228

__global__ __launch_bounds__(THREADS, 1) void k_mpm(
    const void* __restrict__ ei_raw,
    const float* __restrict__ x_in,
    float* __restrict__ out)
{
    extern __shared__ char sm[];
    uint8_t*  smK    = (uint8_t*)sm;
    float*    msgs   = (float*)(sm + 147456);
    uint4*    xq     = (uint4*)(sm + 184320);
    float*    outv   = (float*)(sm + 188416);
    uint32_t* slots  = (uint32_t*)(sm + 192512);
    uint16_t* esrc   = (uint16_t*)(sm + 193664);
    uint16_t* edst   = (uint16_t*)(sm + 194240);
    uint16_t* glist  = (uint16_t*)(sm + 194816);
    uint16_t* dsort  = (uint16_t*)(sm + 195392);
    int*      goff   = (int*)(sm + 195968);
    float*    red    = (float*)(sm + 196100);

    const int tid  = threadIdx.x;
    const int g    = blockIdx.x;
    const int wid  = tid >> 5, lane = tid & 31;

    // ---- int32/int64 detection (warp 0, broadcast through red[31]) ----
    if (tid < 32) {
        unsigned long long v = ((const unsigned long long*)ei_raw)[1 + (lane & 15)];
        unsigned bal = __ballot_sync(0xFFFFFFFFu, v < 4096ull);
        if (lane == 0) red[31] = (bal == 0xFFFFFFFFu) ? 1.0f : 0.0f;
    }
    __syncthreads();
    const int is64 = (red[31] != 0.0f);

    // ---- per-graph edge tables ----
    if (tid < EDGES_G) {
        int k = tid;
        int e = krow(g, k);
        long long s, d;
        if (is64) {
            const long long* p = (const long long*)ei_raw;
            s = p[e]; d = p[E_TOT + e];
        } else {
            const int* p = (const int*)ei_raw;
            s = p[e]; d = p[E_TOT + e];
        }
        esrc[k] = (uint16_t)(s - (long long)g * NV);
        edst[k] = (uint16_t)(d - (long long)g * NV);
    }
    __syncthreads();

    // ---- build (a) per-src gather lists, (b) dst-sorted slot words ----
    if (tid == 0) {
        int cnt[NV];
        #pragma unroll
        for (int s = 0; s < NV; s++) cnt[s] = 0;
        for (int k = 0; k < EDGES_G; k++) cnt[esrc[k]]++;
        int off = 0;
        for (int s = 0; s < NV; s++) { goff[s] = off; off += cnt[s]; cnt[s] = goff[s]; }
        goff[NV] = off;
        for (int k = 0; k < EDGES_G; k++) { int s = esrc[k]; glist[cnt[s]++] = (uint16_t)k; }
    } else if (tid == 32) {
        int dc[NV];
        #pragma unroll
        for (int d = 0; d < NV; d++) dc[d] = 0;
        for (int k = 0; k < EDGES_G; k++) dc[edst[k]]++;
        int off = 0;
        #pragma unroll
        for (int d = 0; d < NV; d++) { int c = dc[d]; dc[d] = off; off += c; }
        for (int k = 0; k < EDGES_G; k++) { int d = edst[k]; dsort[dc[d]++] = (uint16_t)k; }
        int dprev = -1;
        for (int idx = 0; idx < EDGES_G; idx++) {
            int k = dsort[idx];
            int d = edst[k];
            uint32_t flag = ((idx % EPW) == 0 || d != dprev) ? 1u : 0u;
            slots[idx] = (uint32_t)krow(g, k) | ((uint32_t)k << 16)
                       | ((uint32_t)d << 25) | (flag << 30);
            dprev = d;
        }
    }
    __syncthreads();   // slots visible for staging

    // ---- stage K for the first SPW slots of each warp into SMEM ----
    // smK[ss][h*512 + l*16] = g_K8[row(ss)][l*32 + h*16]  (conflict-free reads later)
    for (int c = tid; c < NSTAGE_T * 64; c += THREADS) {
        int ss = c >> 6, u = c & 63;          // u = l*2 + h
        int idx = (ss / SPW) * EPW + (ss % SPW);
        int row = slots[idx] & 0xFFFF;
        int l = u >> 1, h = u & 1;
        *(uint4*)(smK + ss * 1024 + h * 512 + l * 16) =
            *(const uint4*)(g_K8 + (size_t)row * NN + (size_t)u * 16);
    }

    // ---- x0: load raw x, per-warp norm partial -> red[wid] ----
    {
        float part = 0.f;
        for (int t = tid; t < NN; t += THREADS) {
            float v = x_in[(size_t)g * NN + t];
            outv[t] = v;
            part += v * v;
        }
        #pragma unroll
        for (int o = 16; o > 0; o >>= 1) part += __shfl_down_sync(0xFFFFFFFFu, part, o);
        if (lane == 0) red[wid] = part;
    }

    const __half2 NEG1024 = __float2half2_rn(-1024.f);
    const int sbase = wid * EPW;
    const uint8_t* smKw = smK + (wid * SPW) * 1024;

    for (int it = 0; it < ITERS; it++) {
        __syncthreads();                       // A: partials + outv visible
        float inv = rsqrtf(reduce24(red, lane));

        // ---- pack x^2 as half2 quads: xq[node*8+q] = (X01,Y01,X23,Y23) ----
        if (tid < NV * 8) {
            int node = tid >> 3, q = tid & 7, j0 = q * 4;
            const float* xr = outv + node * NV + j0;
            float v0 = xr[0] * inv, v1 = xr[1] * inv, v2 = xr[2] * inv, v3 = xr[3] * inv;
            __half2 Xa = __floats2half2_rn(v0 * v0, v1 * v1);
            __half2 Xb = __floats2half2_rn(v2 * v2, v3 * v3);
            __half2 Ya = __hmul2(Xa, NEG1024);   // exact (power of two)
            __half2 Yb = __hmul2(Xb, NEG1024);
            uint4 w;
            w.x = *reinterpret_cast<uint32_t*>(&Xa);
            w.y = *reinterpret_cast<uint32_t*>(&Ya);
            w.z = *reinterpret_cast<uint32_t*>(&Xb);
            w.w = *reinterpret_cast<uint32_t*>(&Yb);
            xq[tid] = w;
        }
        __syncthreads();                       // B: xq (and iter-1 smK) visible

        // ---- phase 1: dst-sorted edges; staged K from SMEM, streamed from L1 ----
        // msg[e][i] = sqrt(max_j x2[dst][j] * K2[e][i][j])   (scale-free)
        {
            uint4 xd0, xd1, xd2, xd3, xd4, xd5, xd6, xd7;

            // hoist first streamed edge's K load (covered by staged compute)
            uint32_t slS = slots[sbase + SPW];
            uint4 b0, b1;
            {
                const uint4* p = (const uint4*)(g_K8 + (size_t)(slS & 0xFFFFu) * NN) + lane * 2;
                b0 = p[0]; b1 = p[1];
            }

            // staged edges 0..SPW-1: K from SMEM (conflict-free half-split)
            #pragma unroll
            for (int s = 0; s < SPW; s++) {
                uint32_t sl = slots[sbase + s];
                if (sl & (1u << 30)) {            // warp-uniform dst change
                    const uint4* xp = xq + ((sl >> 25) & 31u) * 8;
                    xd0 = xp[0]; xd1 = xp[1]; xd2 = xp[2]; xd3 = xp[3];
                    xd4 = xp[4]; xd5 = xp[5]; xd6 = xp[6]; xd7 = xp[7];
                }
                uint4 q0 = *(const uint4*)(smKw + s * 1024 + lane * 16);
                uint4 q1 = *(const uint4*)(smKw + s * 1024 + 512 + lane * 16);
                __half2 ma = __float2half2_rn(0.f), mb = ma;
                quad_op(q0.x, xd0, ma, mb);
                quad_op(q0.y, xd1, ma, mb);
                quad_op(q0.z, xd2, ma, mb);
                quad_op(q0.w, xd3, ma, mb);
                quad_op(q1.x, xd4, ma, mb);
                quad_op(q1.y, xd5, ma, mb);
                quad_op(q1.z, xd6, ma, mb);
                quad_op(q1.w, xd7, ma, mb);
                __half2 m2 = __hmax2(ma, mb);
                float m2f = __half2float(__hmax(__low2half(m2), __high2half(m2)));
                float msg;
                asm("sqrt.approx.f32 %0, %1;" : "=f"(msg) : "f"(m2f));
                msgs[((sl >> 16) & 0x1FFu) * NV + lane] = msg;
            }

            // streamed edges SPW..EPW-1: L1-resident after iter 1, depth-1 prefetch
            uint32_t sl = slS;
            uint4 q0 = b0, q1 = b1;
            #pragma unroll
            for (int s = SPW; s < EPW; s++) {
                uint32_t sln;
                uint4 n0, n1;
                if (s + 1 < EPW) {
                    sln = slots[sbase + s + 1];
                    const uint4* pn = (const uint4*)(g_K8 + (size_t)(sln & 0xFFFFu) * NN) + lane * 2;
                    n0 = pn[0]; n1 = pn[1];
                }
                if (sl & (1u << 30)) {
                    const uint4* xp = xq + ((sl >> 25) & 31u) * 8;
                    xd0 = xp[0]; xd1 = xp[1]; xd2 = xp[2]; xd3 = xp[3];
                    xd4 = xp[4]; xd5 = xp[5]; xd6 = xp[6]; xd7 = xp[7];
                }
                __half2 ma = __float2half2_rn(0.f), mb = ma;
                quad_op(q0.x, xd0, ma, mb);
                quad_op(q0.y, xd1, ma, mb);
                quad_op(q0.z, xd2, ma, mb);
                quad_op(q0.w, xd3, ma, mb);
                quad_op(q1.x, xd4, ma, mb);
                quad_op(q1.y, xd5, ma, mb);
                quad_op(q1.z, xd6, ma, mb);
                quad_op(q1.w, xd7, ma, mb);
                __half2 m2 = __hmax2(ma, mb);
                float m2f = __half2float(__hmax(__low2half(m2), __high2half(m2)));
                float msg;
                asm("sqrt.approx.f32 %0, %1;" : "=f"(msg) : "f"(m2f));
                msgs[((sl >> 16) & 0x1FFu) * NV + lane] = msg;
                if (s + 1 < EPW) { sl = sln; q0 = n0; q1 = n1; }
            }
        }
        __syncthreads();                       // C: msgs visible

        // ---- phase 2: segment-sum over src (two strided passes) + norm partial ----
        float part;
        {
            int s = tid >> 5, i = tid & 31;    // s warp-uniform -> broadcast list loads
            float a = 0.f;
            int b = goff[s], e2 = goff[s + 1];
            for (int q = b; q < e2; q++)
                a += msgs[(int)glist[q] * NV + i];
            outv[tid] = a;
            part = a * a;
        }
        if (tid < NN - THREADS) {              // remaining 256 elements (s = 24..31)
            int t = tid + THREADS;
            int s = t >> 5, i = t & 31;
            float a = 0.f;
            int b = goff[s], e2 = goff[s + 1];
            for (int q = b; q < e2; q++)
                a += msgs[(int)glist[q] * NV + i];
            outv[t] = a;
            part += a * a;
        }
        #pragma unroll
        for (int o = 16; o > 0; o >>= 1) part += __shfl_down_sync(0xFFFFFFFFu, part, o);
        if (lane == 0) red[wid] = part;
        // outv stays unnormalized; total published at next iteration's sync A
    }

    // ---- output: out[g, i, s] = x[g*32+s, i]  (transpose last two dims) ----
    __syncthreads();
    {
        float inv = rsqrtf(reduce24(red, lane));
        for (int t = tid; t < NN; t += THREADS) {
            int i = t >> 5, s = t & 31;
            out[(size_t)g * NN + t] = outv[s * NV + i] * inv;
        }
    }
}

// ---------------------------------------------------------------------------
extern "C" void kernel_launch(void* const* d_in, const int* in_sizes, int n_in,
                              void* d_out, int out_size) {
    const float* K  = (const float*)d_in[0];
    const void*  ei = d_in[1];
    const float* x  = (const float*)d_in[2];
    float* out = (float*)d_out;

    (void)in_sizes; (void)n_in; (void)out_size;

    cudaFuncSetAttribute(k_mpm, cudaFuncAttributeMaxDynamicSharedMemorySize, SMEM_BYTES);

    // 36864*1024 elems / 16 per thread / 256 per block = 9216 blocks (exact)
    k_convert<<<9216, 256>>>(K);

    k_mpm<<<BSZ, THREADS, SMEM_BYTES>>>(ei, x, out);
}